// round 7
// baseline (speedup 1.0000x reference)
#include <cuda_runtime.h>
#include <math.h>

#define BB 4
#define NN 2048
#define MM 16
#define SS 200
#define CHUNKS 8            // N split into 8 chunks of 256 (producer side)

#define P2P_BLOCKS   (BB * MM * CHUNKS)        // 512
#define PRIM_BLOCKS  (BB * MM * CHUNKS)        // 512
#define PROD_BLOCKS  (P2P_BLOCKS + PRIM_BLOCKS + 1)   // 1025 (last = emb)
#define TAIL_P2P     (BB * 16)                 // 64 blocks x 128 points
#define TAIL_PRIM    8
#define TAIL_BLOCKS  (TAIL_P2P + TAIL_PRIM)    // 72
#define GRID_BLOCKS  (PROD_BLOCKS + TAIL_BLOCKS)

typedef unsigned long long ull;

// ---------------- device scratch ----------------
__device__ float    g_dv[BB * NN * MM];                 // TRANSPOSED: [(b*NN+n)*MM + m]
__device__ float    g_dpart[BB * MM * CHUNKS * SS];     // per-chunk partial min-over-n
__device__ double   g_part[TAIL_BLOCKS];                // per-tail-block partial sums
__device__ double   g_emb;
__device__ unsigned g_cnt1;                             // producer ticket (self-resetting)
__device__ unsigned g_cnt2;                             // tail ticket (self-resetting)

// ---------------- f32x2 packed helpers (sm_100) ----------------
__device__ __forceinline__ ull pk2(float lo, float hi) {
    ull r; asm("mov.b64 %0, {%1, %2};" : "=l"(r) : "f"(lo), "f"(hi)); return r;
}
__device__ __forceinline__ ull fma2(ull a, ull b, ull c) {
    ull r; asm("fma.rn.f32x2 %0, %1, %2, %3;" : "=l"(r) : "l"(a), "l"(b), "l"(c)); return r;
}
__device__ __forceinline__ void upk2(ull v, float& lo, float& hi) {
    asm("mov.b64 {%0, %1}, %2;" : "=f"(lo), "=f"(hi) : "l"(v));
}

__device__ __forceinline__ float fexp_f(float x, float p) {
    float s = (x > 0.f) ? 1.f : ((x < 0.f) ? -1.f : 0.f);
    return s * powf(fabsf(x) + 1e-6f, p);
}

__device__ __forceinline__ double blockReduceSumD(double v) {
    __shared__ double sh[32];
    int lane = threadIdx.x & 31, wid = threadIdx.x >> 5;
    #pragma unroll
    for (int o = 16; o; o >>= 1) v += __shfl_down_sync(0xffffffffu, v, o);
    if (lane == 0) sh[wid] = v;
    __syncthreads();
    int nw = (blockDim.x + 31) >> 5;
    v = (threadIdx.x < nw) ? sh[threadIdx.x] : 0.0;
    if (wid == 0) {
        #pragma unroll
        for (int o = 16; o; o >>= 1) v += __shfl_down_sync(0xffffffffu, v, o);
    }
    __syncthreads();
    return v;
}

// argmax_i emb[b][i][m]  (first max on ties)
__device__ __forceinline__ int argmax_col(const float* __restrict__ emb, int b, int m) {
    int j = 0;
    float best = emb[(b * MM + 0) * MM + m];
    #pragma unroll
    for (int i = 1; i < MM; i++) {
        float v = emb[(b * MM + i) * MM + m];
        if (v > best) { best = v; j = i; }
    }
    return j;
}

// ---------------- THE kernel ----------------
__global__ void __launch_bounds__(256) k_all(const float* __restrict__ pcl,
                                             const float* __restrict__ trans,
                                             const float* __restrict__ rot,
                                             const float* __restrict__ size,
                                             const float* __restrict__ shape,
                                             const float* __restrict__ deform,
                                             const float* __restrict__ prob,
                                             const float* __restrict__ emb,
                                             float* __restrict__ out)
{
    int bid = blockIdx.x, t = threadIdx.x;

    // ===================== PRODUCER BLOCKS =====================
    if (bid < PROD_BLOCKS) {
        if (bid == PROD_BLOCKS - 1) {
            // ---- embeddings regularizer ----
            double c1 = 0.0, c2 = 0.0, c3 = 0.0;
            if (t < BB * MM) {
                int bb = t / MM, k = t % MM;
                float s1 = 0.f, s2 = 0.f;
                for (int i = 0; i < MM; i++) {
                    s1 += emb[(bb * MM + i) * MM + k];
                    s2 += emb[(bb * MM + k) * MM + i];
                }
                float d1 = s1 - 1.f, d2 = s2 - 1.f;
                c1 = (double)(d1 * d1);
                c2 = (double)(d2 * d2);
            }
            for (int i = t; i < BB * MM * MM; i += 256) {
                float v = emb[i];
                c3 += (double)(v * (1.f - v));
            }
            double r1 = blockReduceSumD(c1);
            double r2 = blockReduceSumD(c2);
            double r3 = blockReduceSumD(c3);
            if (t == 0) {
                g_emb = r1 / (double)(BB * MM) + 10.0 * r2 / (double)(BB * MM)
                      + r3 / (double)(BB * MM * MM);
                __threadfence();
                atomicAdd(&g_cnt1, 1u);
            }
            return;
        }

        // packed-pair layout: s_qA[p] = ((x0,x1),(y0,y1)), s_qB[p] = ((z0,z1),(w0,w1))
        __shared__ ulonglong2 s_qA[SS / 2], s_qB[SS / 2];
        __shared__ ulonglong2 s_uA[128], s_uB[128];
        __shared__ float  s_R[9], s_t[3], s_par[7];

        int side  = (bid >= P2P_BLOCKS);           // 0 = p2p, 1 = prim
        int pid   = side ? bid - P2P_BLOCKS : bid;
        int blkm  = pid / CHUNKS;
        int chunk = pid % CHUNKS;
        int b     = blkm / MM, m = blkm % MM;

        if (t == 0) {
            int j = argmax_col(emb, b, m);
            const float* q = rot + blkm * 4;
            float w = q[0], x = q[1], y = q[2], z = q[3];
            float inv = rsqrtf(w * w + x * x + y * y + z * z);
            w *= inv; x *= inv; y *= inv; z *= inv;
            s_R[0] = 1.f - 2.f * (y * y + z * z); s_R[1] = 2.f * (x * y - w * z); s_R[2] = 2.f * (x * z + w * y);
            s_R[3] = 2.f * (x * y + w * z); s_R[4] = 1.f - 2.f * (x * x + z * z); s_R[5] = 2.f * (y * z - w * x);
            s_R[6] = 2.f * (x * z - w * y); s_R[7] = 2.f * (y * z + w * x); s_R[8] = 1.f - 2.f * (x * x + y * y);
            s_t[0] = trans[blkm * 3 + 0]; s_t[1] = trans[blkm * 3 + 1]; s_t[2] = trans[blkm * 3 + 2];
            const float* sz3 = size   + (b * MM + j) * 3;
            const float* sh2 = shape  + (b * MM + j) * 2;
            const float* df2 = deform + (b * MM + j) * 2;
            s_par[0] = sh2[0]; s_par[1] = sh2[1];
            s_par[2] = sz3[0]; s_par[3] = sz3[1]; s_par[4] = sz3[2];
            s_par[5] = df2[0]; s_par[6] = df2[1];
        }
        __syncthreads();

        // sample points — written scalar into packed-pair layout
        if (t < SS) {
            float e1 = s_par[0], e2 = s_par[1];
            float sx = s_par[2], sy = s_par[3], szv = s_par[4];
            float dfx = s_par[5], dfy = s_par[6];
            double stepE = (M_PI - 0.1) / (double)(SS - 1);
            double stepO = (2.0 * M_PI - 0.1) / (double)(SS - 1);
            float eta = (float)(-M_PI / 2.0 + 0.05 + t * stepE);
            float omg = (float)(-M_PI + 0.05 + t * stepO);
            float ce = cosf(eta), se = sinf(eta), co = cosf(omg), so = sinf(omg);
            float fce = fexp_f(ce, e1);
            float x = sx * fce * fexp_f(co, e2);
            float y = sy * fce * fexp_f(so, e2);
            float z = szv * fexp_f(se, e1);
            float fx = dfx / szv * z + 1.f;
            float fy = dfy / szv * z + 1.f;
            float X = x * fx, Y = y * fy, Z = z;
            float W = fmaf(X, X, fmaf(Y, Y, Z * Z));
            int p = t >> 1, h = t & 1;
            float* A = (float*)s_qA;  float* Bf = (float*)s_qB;
            A[4 * p + h]     = X;  A[4 * p + 2 + h] = Y;
            Bf[4 * p + h]    = Z;  Bf[4 * p + 2 + h] = W;
        }
        if (side) {
            int n = chunk * 256 + t;
            const float* P = pcl + (b * NN + n) * 3;
            float ax = P[0] - s_t[0], ay = P[1] - s_t[1], az = P[2] - s_t[2];
            float ux = s_R[0] * ax + s_R[1] * ay + s_R[2] * az;
            float uy = s_R[3] * ax + s_R[4] * ay + s_R[5] * az;
            float uz = s_R[6] * ax + s_R[7] * ay + s_R[8] * az;
            float uw = fmaf(ux, ux, fmaf(uy, uy, uz * uz));
            int p = t >> 1, h = t & 1;
            float* A = (float*)s_uA;  float* Bf = (float*)s_uB;
            A[4 * p + h]     = ux; A[4 * p + 2 + h] = uy;
            Bf[4 * p + h]    = uz; Bf[4 * p + 2 + h] = uw;
        }
        __syncthreads();

        if (!side) {
            // ---------- pcl -> prim: min over S (packed f32x2, zero pack-movs) ----------
            int n = chunk * 256 + t;
            const float* P = pcl + (b * NN + n) * 3;
            float ax = P[0] - s_t[0], ay = P[1] - s_t[1], az = P[2] - s_t[2];
            float tx = s_R[0] * ax + s_R[1] * ay + s_R[2] * az;
            float ty = s_R[3] * ax + s_R[4] * ay + s_R[5] * az;
            float tz = s_R[6] * ax + s_R[7] * ay + s_R[8] * az;
            float tt  = fmaf(tx, tx, fmaf(ty, ty, tz * tz));
            ull tx2p = pk2(-2.f * tx, -2.f * tx);
            ull ty2p = pk2(-2.f * ty, -2.f * ty);
            ull tz2p = pk2(-2.f * tz, -2.f * tz);

            float m0 = 3.4e38f, m1 = m0, m2 = m0, m3 = m0;
            #pragma unroll 5
            for (int p = 0; p < SS / 2; p += 2) {
                ulonglong2 a0 = s_qA[p],     b0 = s_qB[p];
                ulonglong2 a1 = s_qA[p + 1], b1 = s_qB[p + 1];
                ull v0 = fma2(b0.x, tz2p, b0.y);
                v0 = fma2(a0.y, ty2p, v0);
                v0 = fma2(a0.x, tx2p, v0);
                float l0, h0; upk2(v0, l0, h0);
                m0 = fminf(m0, l0); m1 = fminf(m1, h0);
                ull v1 = fma2(b1.x, tz2p, b1.y);
                v1 = fma2(a1.y, ty2p, v1);
                v1 = fma2(a1.x, tx2p, v1);
                float l1, h1; upk2(v1, l1, h1);
                m2 = fminf(m2, l1); m3 = fminf(m3, h1);
            }
            float d = fminf(fminf(m0, m1), fminf(m2, m3)) + tt;
            d = fmaxf(d, 0.f);
            g_dv[(b * NN + n) * MM + m] = d;   // transposed store
        } else {
            // ---------- prim -> pcl: partial min over this chunk's 256 points ----------
            if (t < SS) {
                int p0 = t >> 1, h0i = t & 1;
                const float* A = (const float*)s_qA;  const float* Bf = (const float*)s_qB;
                float qx = A[4 * p0 + h0i], qy = A[4 * p0 + 2 + h0i];
                float qz = Bf[4 * p0 + h0i], qw = Bf[4 * p0 + 2 + h0i];
                ull qx2p = pk2(-2.f * qx, -2.f * qx);
                ull qy2p = pk2(-2.f * qy, -2.f * qy);
                ull qz2p = pk2(-2.f * qz, -2.f * qz);

                float m0 = 3.4e38f, m1 = m0, m2 = m0, m3 = m0;
                #pragma unroll 4
                for (int p = 0; p < 128; p += 2) {
                    ulonglong2 a0 = s_uA[p],     b0 = s_uB[p];
                    ulonglong2 a1 = s_uA[p + 1], b1 = s_uB[p + 1];
                    ull v0 = fma2(b0.x, qz2p, b0.y);
                    v0 = fma2(a0.y, qy2p, v0);
                    v0 = fma2(a0.x, qx2p, v0);
                    float l0, h0; upk2(v0, l0, h0);
                    m0 = fminf(m0, l0); m1 = fminf(m1, h0);
                    ull v1 = fma2(b1.x, qz2p, b1.y);
                    v1 = fma2(a1.y, qy2p, v1);
                    v1 = fma2(a1.x, qx2p, v1);
                    float l1, h1; upk2(v1, l1, h1);
                    m2 = fminf(m2, l1); m3 = fminf(m3, h1);
                }
                float d = fminf(fminf(m0, m1), fminf(m2, m3)) + qw;
                d = fmaxf(d, 0.f);
                g_dpart[(blkm * CHUNKS + chunk) * SS + t] = d;
            }
        }

        __syncthreads();
        if (t == 0) {
            __threadfence();
            atomicAdd(&g_cnt1, 1u);
        }
        return;
    }

    // ===================== TAIL BLOCKS (spin until producers done) =====================
    if (t == 0) {
        volatile unsigned* c = &g_cnt1;
        while (*c < (unsigned)PROD_BLOCKS) __nanosleep(64);
    }
    __syncthreads();
    __threadfence();   // order subsequent reads after observed release

    int pid = bid - PROD_BLOCKS;   // 0..71
    double part = 0.0;

    if (pid < TAIL_P2P) {
        // ---- p2p weighting: 64 blocks x 128 points ----
        __shared__ float s_p[MM];
        int b = pid / 16, c16 = pid % 16;
        if (t < MM) s_p[t] = prob[b * MM + t];
        __syncthreads();

        float acc = 0.f;
        if (t < 128) {
            int n = c16 * 128 + t;
            const float4* dvp = (const float4*)&g_dv[(b * NN + n) * MM];
            float dv[MM], pv[MM];
            float4 d0 = __ldcg(&dvp[0]), d1 = __ldcg(&dvp[1]);
            float4 d2 = __ldcg(&dvp[2]), d3 = __ldcg(&dvp[3]);
            ((float4*)dv)[0] = d0; ((float4*)dv)[1] = d1;
            ((float4*)dv)[2] = d2; ((float4*)dv)[3] = d3;
            #pragma unroll
            for (int mm = 0; mm < MM; mm++) pv[mm] = s_p[mm];

            #pragma unroll
            for (int mm = 0; mm < MM; mm++) {
                float w = pv[mm];
                #pragma unroll
                for (int j = 0; j < MM; j++) {
                    if (j == mm) continue;
                    bool before = (dv[j] < dv[mm]) || (dv[j] == dv[mm] && j < mm);
                    w *= before ? (1.f - pv[j]) : 1.f;
                }
                acc = fmaf(dv[mm], w, acc);
            }
        }
        part = blockReduceSumD((double)acc) / (double)(BB * NN);
    } else {
        // ---- prim partial reduction: 8 blkm per block ----
        int pid2 = pid - TAIL_P2P;               // 0..7
        int blkm0 = pid2 * 8;
        int b = blkm0 / MM;
        __shared__ float s_a[MM];
        __shared__ float s_w[8];

        if (t < MM) {
            int j = argmax_col(emb, b, t);
            const float* sz3 = size + (b * MM + j) * 3;
            float a0 = sz3[0], a1 = sz3[1], a2 = sz3[2];
            float ar = powf(a0 * a1, 1.6f) / 3.f + powf(a0 * a2, 1.6f) / 3.f + powf(a1 * a2, 1.6f) / 3.f;
            s_a[t] = 4.f * (float)M_PI * powf(ar, 0.625f);
        }
        __syncthreads();
        if (t < 8) {
            float sa = 0.f;
            #pragma unroll
            for (int mm = 0; mm < MM; mm++) sa += s_a[mm];
            int m_in_b = (blkm0 % MM) + t;
            s_w[t] = s_a[m_in_b] / sa / (float)(SS * BB);
        }
        __syncthreads();

        double acc = 0.0;
        for (int i = t; i < 8 * SS; i += 256) {
            int bl = i / SS, s = i % SS;
            const float* base = g_dpart + ((blkm0 + bl) * CHUNKS) * SS + s;
            float v = __ldcg(&base[0]);
            #pragma unroll
            for (int c = 1; c < CHUNKS; c++) v = fminf(v, __ldcg(&base[c * SS]));
            v = (v >= 1e30f) ? 0.f : v;
            acc += (double)(v * s_w[bl]);
        }
        part = blockReduceSumD(acc);
    }

    __shared__ bool s_last;
    if (t == 0) g_part[pid] = part;
    __threadfence();
    if (t == 0) {
        unsigned tk = atomicAdd(&g_cnt2, 1u);
        s_last = (tk == (unsigned)(TAIL_BLOCKS - 1));
    }
    __syncthreads();

    if (s_last && t == 0) {
        double p2p = 0.0, prim = 0.0;
        #pragma unroll
        for (int i = 0; i < TAIL_P2P; i++)  p2p  += __ldcg(&g_part[i]);
        #pragma unroll
        for (int i = TAIL_P2P; i < TAIL_BLOCKS; i++) prim += __ldcg(&g_part[i]);
        double embv = __ldcg(&g_emb);
        out[0] = (float)(p2p + prim + embv);
        out[1] = (float)p2p;
        out[2] = (float)prim;
        out[3] = 0.f;
        out[4] = (float)embv;
        g_cnt1 = 0;   // reset for next graph replay
        g_cnt2 = 0;
    }
}

// ---------------- launch ----------------
extern "C" void kernel_launch(void* const* d_in, const int* in_sizes, int n_in,
                              void* d_out, int out_size)
{
    const float* pcl    = (const float*)d_in[0];
    const float* trans  = (const float*)d_in[1];
    const float* rot    = (const float*)d_in[2];
    const float* size   = (const float*)d_in[3];
    const float* shape  = (const float*)d_in[4];
    const float* deform = (const float*)d_in[5];
    const float* prob   = (const float*)d_in[6];
    const float* emb    = (const float*)d_in[7];

    k_all<<<GRID_BLOCKS, 256>>>(pcl, trans, rot, size, shape, deform, prob, emb,
                                (float*)d_out);
}

// round 8
// speedup vs baseline: 1.0514x; 1.0514x over previous
#include <cuda_runtime.h>
#include <math.h>

#define BB 4
#define NN 2048
#define MM 16
#define SS 200
#define CHUNKS 8            // N split into 8 chunks of 256 (producer side)

#define P2P_BLOCKS   (BB * MM * CHUNKS)        // 512
#define FUSED_BLOCKS (P2P_BLOCKS * 2)          // 1024 (+1 emb block)
#define TAIL_P2P     (BB * 16)                 // 64 blocks x 128 points
#define TAIL_PRIM    (BB * MM)                 // 64 blocks, one per (b,m)
#define TAIL_BLOCKS  (TAIL_P2P + TAIL_PRIM)    // 128

typedef unsigned long long ull;

// ---------------- device scratch ----------------
__device__ float    g_dv[BB * NN * MM];                 // TRANSPOSED: [(b*NN+n)*MM + m]
__device__ float    g_dpart[BB * MM * CHUNKS * SS];     // per-chunk partial min-over-n
__device__ double   g_part[TAIL_BLOCKS];                // per-tail-block partial sums
__device__ double   g_emb;
__device__ unsigned g_cnt;                              // tail ticket (self-resetting)

// ---------------- f32x2 packed helpers (sm_100) ----------------
__device__ __forceinline__ ull pk2(float lo, float hi) {
    ull r; asm("mov.b64 %0, {%1, %2};" : "=l"(r) : "f"(lo), "f"(hi)); return r;
}
__device__ __forceinline__ ull fma2(ull a, ull b, ull c) {
    ull r; asm("fma.rn.f32x2 %0, %1, %2, %3;" : "=l"(r) : "l"(a), "l"(b), "l"(c)); return r;
}
__device__ __forceinline__ void upk2(ull v, float& lo, float& hi) {
    asm("mov.b64 {%0, %1}, %2;" : "=f"(lo), "=f"(hi) : "l"(v));
}

__device__ __forceinline__ float fexp_f(float x, float p) {
    float s = (x > 0.f) ? 1.f : ((x < 0.f) ? -1.f : 0.f);
    return s * powf(fabsf(x) + 1e-6f, p);
}

__device__ __forceinline__ double blockReduceSumD(double v) {
    __shared__ double sh[32];
    int lane = threadIdx.x & 31, wid = threadIdx.x >> 5;
    #pragma unroll
    for (int o = 16; o; o >>= 1) v += __shfl_down_sync(0xffffffffu, v, o);
    if (lane == 0) sh[wid] = v;
    __syncthreads();
    int nw = (blockDim.x + 31) >> 5;
    v = (threadIdx.x < nw) ? sh[threadIdx.x] : 0.0;
    if (wid == 0) {
        #pragma unroll
        for (int o = 16; o; o >>= 1) v += __shfl_down_sync(0xffffffffu, v, o);
    }
    __syncthreads();
    return v;
}

// argmax_i emb[b][i][m]  (first max on ties)
__device__ __forceinline__ int argmax_col(const float* __restrict__ emb, int b, int m) {
    int j = 0;
    float best = emb[(b * MM + 0) * MM + m];
    #pragma unroll
    for (int i = 1; i < MM; i++) {
        float v = emb[(b * MM + i) * MM + m];
        if (v > best) { best = v; j = i; }
    }
    return j;
}

// ---------------- kernel 1: fused prep + distance field (+1 emb block) ----------------
__global__ void __launch_bounds__(256, 5) k_fused(const float* __restrict__ pcl,
                                                  const float* __restrict__ trans,
                                                  const float* __restrict__ rot,
                                                  const float* __restrict__ size,
                                                  const float* __restrict__ shape,
                                                  const float* __restrict__ deform,
                                                  const float* __restrict__ emb)
{
    int bid = blockIdx.x, t = threadIdx.x;

    if (bid == FUSED_BLOCKS) {
        // ---- embeddings regularizer ----
        double c1 = 0.0, c2 = 0.0, c3 = 0.0;
        if (t < BB * MM) {
            int bb = t / MM, k = t % MM;
            float s1 = 0.f, s2 = 0.f;
            for (int i = 0; i < MM; i++) {
                s1 += emb[(bb * MM + i) * MM + k];
                s2 += emb[(bb * MM + k) * MM + i];
            }
            float d1 = s1 - 1.f, d2 = s2 - 1.f;
            c1 = (double)(d1 * d1);
            c2 = (double)(d2 * d2);
        }
        for (int i = t; i < BB * MM * MM; i += 256) {
            float v = emb[i];
            c3 += (double)(v * (1.f - v));
        }
        double r1 = blockReduceSumD(c1);
        double r2 = blockReduceSumD(c2);
        double r3 = blockReduceSumD(c3);
        if (t == 0)
            g_emb = r1 / (double)(BB * MM) + 10.0 * r2 / (double)(BB * MM)
                  + r3 / (double)(BB * MM * MM);
        return;
    }

    // packed-pair layout: s_qA[p] = ((x0,x1),(y0,y1)), s_qB[p] = ((z0,z1),(w0,w1))
    __shared__ ulonglong2 s_qA[SS / 2], s_qB[SS / 2];
    __shared__ ulonglong2 s_uA[128], s_uB[128];
    __shared__ float  s_R[9], s_t[3], s_par[7];

    int side  = (bid >= P2P_BLOCKS);           // 0 = p2p, 1 = prim
    int pid   = side ? bid - P2P_BLOCKS : bid;
    int blkm  = pid / CHUNKS;
    int chunk = pid % CHUNKS;
    int b     = blkm / MM, m = blkm % MM;

    if (t == 0) {
        int j = argmax_col(emb, b, m);
        const float* q = rot + blkm * 4;
        float w = q[0], x = q[1], y = q[2], z = q[3];
        float inv = rsqrtf(w * w + x * x + y * y + z * z);
        w *= inv; x *= inv; y *= inv; z *= inv;
        s_R[0] = 1.f - 2.f * (y * y + z * z); s_R[1] = 2.f * (x * y - w * z); s_R[2] = 2.f * (x * z + w * y);
        s_R[3] = 2.f * (x * y + w * z); s_R[4] = 1.f - 2.f * (x * x + z * z); s_R[5] = 2.f * (y * z - w * x);
        s_R[6] = 2.f * (x * z - w * y); s_R[7] = 2.f * (y * z + w * x); s_R[8] = 1.f - 2.f * (x * x + y * y);
        s_t[0] = trans[blkm * 3 + 0]; s_t[1] = trans[blkm * 3 + 1]; s_t[2] = trans[blkm * 3 + 2];
        const float* sz3 = size   + (b * MM + j) * 3;
        const float* sh2 = shape  + (b * MM + j) * 2;
        const float* df2 = deform + (b * MM + j) * 2;
        s_par[0] = sh2[0]; s_par[1] = sh2[1];
        s_par[2] = sz3[0]; s_par[3] = sz3[1]; s_par[4] = sz3[2];
        s_par[5] = df2[0]; s_par[6] = df2[1];
    }
    __syncthreads();

    // sample points — written scalar into packed-pair layout
    if (t < SS) {
        float e1 = s_par[0], e2 = s_par[1];
        float sx = s_par[2], sy = s_par[3], szv = s_par[4];
        float dfx = s_par[5], dfy = s_par[6];
        double stepE = (M_PI - 0.1) / (double)(SS - 1);
        double stepO = (2.0 * M_PI - 0.1) / (double)(SS - 1);
        float eta = (float)(-M_PI / 2.0 + 0.05 + t * stepE);
        float omg = (float)(-M_PI + 0.05 + t * stepO);
        float ce = cosf(eta), se = sinf(eta), co = cosf(omg), so = sinf(omg);
        float fce = fexp_f(ce, e1);
        float x = sx * fce * fexp_f(co, e2);
        float y = sy * fce * fexp_f(so, e2);
        float z = szv * fexp_f(se, e1);
        float fx = dfx / szv * z + 1.f;
        float fy = dfy / szv * z + 1.f;
        float X = x * fx, Y = y * fy, Z = z;
        float W = fmaf(X, X, fmaf(Y, Y, Z * Z));
        int p = t >> 1, h = t & 1;
        float* A = (float*)s_qA;  float* Bf = (float*)s_qB;
        A[4 * p + h]     = X;  A[4 * p + 2 + h] = Y;
        Bf[4 * p + h]    = Z;  Bf[4 * p + 2 + h] = W;
    }
    if (side) {
        int n = chunk * 256 + t;
        const float* P = pcl + (b * NN + n) * 3;
        float ax = P[0] - s_t[0], ay = P[1] - s_t[1], az = P[2] - s_t[2];
        float ux = s_R[0] * ax + s_R[1] * ay + s_R[2] * az;
        float uy = s_R[3] * ax + s_R[4] * ay + s_R[5] * az;
        float uz = s_R[6] * ax + s_R[7] * ay + s_R[8] * az;
        float uw = fmaf(ux, ux, fmaf(uy, uy, uz * uz));
        int p = t >> 1, h = t & 1;
        float* A = (float*)s_uA;  float* Bf = (float*)s_uB;
        A[4 * p + h]     = ux; A[4 * p + 2 + h] = uy;
        Bf[4 * p + h]    = uz; Bf[4 * p + 2 + h] = uw;
    }
    __syncthreads();

    if (!side) {
        // ---------- pcl -> prim: min over S (packed f32x2) ----------
        int n = chunk * 256 + t;
        const float* P = pcl + (b * NN + n) * 3;
        float ax = P[0] - s_t[0], ay = P[1] - s_t[1], az = P[2] - s_t[2];
        float tx = s_R[0] * ax + s_R[1] * ay + s_R[2] * az;
        float ty = s_R[3] * ax + s_R[4] * ay + s_R[5] * az;
        float tz = s_R[6] * ax + s_R[7] * ay + s_R[8] * az;
        float tt  = fmaf(tx, tx, fmaf(ty, ty, tz * tz));
        ull tx2p = pk2(-2.f * tx, -2.f * tx);
        ull ty2p = pk2(-2.f * ty, -2.f * ty);
        ull tz2p = pk2(-2.f * tz, -2.f * tz);

        float m0 = 3.4e38f, m1 = m0, m2 = m0, m3 = m0;
        #pragma unroll 5
        for (int p = 0; p < SS / 2; p += 2) {
            ulonglong2 a0 = s_qA[p],     b0 = s_qB[p];
            ulonglong2 a1 = s_qA[p + 1], b1 = s_qB[p + 1];
            ull v0 = fma2(b0.x, tz2p, b0.y);
            v0 = fma2(a0.y, ty2p, v0);
            v0 = fma2(a0.x, tx2p, v0);
            float l0, h0; upk2(v0, l0, h0);
            m0 = fminf(m0, l0); m1 = fminf(m1, h0);
            ull v1 = fma2(b1.x, tz2p, b1.y);
            v1 = fma2(a1.y, ty2p, v1);
            v1 = fma2(a1.x, tx2p, v1);
            float l1, h1; upk2(v1, l1, h1);
            m2 = fminf(m2, l1); m3 = fminf(m3, h1);
        }
        float d = fminf(fminf(m0, m1), fminf(m2, m3)) + tt;
        d = fmaxf(d, 0.f);
        g_dv[(b * NN + n) * MM + m] = d;   // transposed store
    } else {
        // ---------- prim -> pcl: partial min over this chunk's 256 points ----------
        if (t < SS) {
            int p0 = t >> 1, h0i = t & 1;
            const float* A = (const float*)s_qA;  const float* Bf = (const float*)s_qB;
            float qx = A[4 * p0 + h0i], qy = A[4 * p0 + 2 + h0i];
            float qz = Bf[4 * p0 + h0i], qw = Bf[4 * p0 + 2 + h0i];
            ull qx2p = pk2(-2.f * qx, -2.f * qx);
            ull qy2p = pk2(-2.f * qy, -2.f * qy);
            ull qz2p = pk2(-2.f * qz, -2.f * qz);

            float m0 = 3.4e38f, m1 = m0, m2 = m0, m3 = m0;
            #pragma unroll 4
            for (int p = 0; p < 128; p += 2) {
                ulonglong2 a0 = s_uA[p],     b0 = s_uB[p];
                ulonglong2 a1 = s_uA[p + 1], b1 = s_uB[p + 1];
                ull v0 = fma2(b0.x, qz2p, b0.y);
                v0 = fma2(a0.y, qy2p, v0);
                v0 = fma2(a0.x, qx2p, v0);
                float l0, h0; upk2(v0, l0, h0);
                m0 = fminf(m0, l0); m1 = fminf(m1, h0);
                ull v1 = fma2(b1.x, qz2p, b1.y);
                v1 = fma2(a1.y, qy2p, v1);
                v1 = fma2(a1.x, qx2p, v1);
                float l1, h1; upk2(v1, l1, h1);
                m2 = fminf(m2, l1); m3 = fminf(m3, h1);
            }
            float d = fminf(fminf(m0, m1), fminf(m2, m3)) + qw;
            d = fmaxf(d, 0.f);
            g_dpart[(blkm * CHUNKS + chunk) * SS + t] = d;
        }
    }
}

// ---------------- kernel 2: tail — 64 p2p blocks + 64 prim blocks, 128 threads ----------------
__global__ void __launch_bounds__(128) k_tail(const float* __restrict__ prob,
                                              const float* __restrict__ size,
                                              const float* __restrict__ emb,
                                              float* __restrict__ out)
{
    __shared__ bool s_last;
    int bid = blockIdx.x, t = threadIdx.x;
    double part = 0.0;

    if (bid < TAIL_P2P) {
        // ---- p2p weighting: 64 blocks x 128 points ----
        __shared__ float s_p[MM];
        int b = bid / 16, c16 = bid % 16;
        if (t < MM) s_p[t] = prob[b * MM + t];
        __syncthreads();

        int n = c16 * 128 + t;
        const float4* dvp = (const float4*)&g_dv[(b * NN + n) * MM];
        float dv[MM], pv[MM];
        float4 d0 = dvp[0], d1 = dvp[1], d2 = dvp[2], d3 = dvp[3];
        ((float4*)dv)[0] = d0; ((float4*)dv)[1] = d1;
        ((float4*)dv)[2] = d2; ((float4*)dv)[3] = d3;
        #pragma unroll
        for (int mm = 0; mm < MM; mm++) pv[mm] = s_p[mm];

        float acc = 0.f;
        #pragma unroll
        for (int mm = 0; mm < MM; mm++) {
            float w = pv[mm];
            #pragma unroll
            for (int j = 0; j < MM; j++) {
                if (j == mm) continue;
                bool before = (dv[j] < dv[mm]) || (dv[j] == dv[mm] && j < mm);
                w *= before ? (1.f - pv[j]) : 1.f;
            }
            acc = fmaf(dv[mm], w, acc);
        }
        part = blockReduceSumD((double)acc) / (double)(BB * NN);
    } else {
        // ---- prim reduction: one block per (b,m) ----
        int blkm = bid - TAIL_P2P;
        int b = blkm / MM;
        __shared__ float s_a[MM];
        __shared__ float s_w[1];

        if (t < MM) {
            int j = argmax_col(emb, b, t);
            const float* sz3 = size + (b * MM + j) * 3;
            float a0 = sz3[0], a1 = sz3[1], a2 = sz3[2];
            float ar = powf(a0 * a1, 1.6f) / 3.f + powf(a0 * a2, 1.6f) / 3.f + powf(a1 * a2, 1.6f) / 3.f;
            s_a[t] = 4.f * (float)M_PI * powf(ar, 0.625f);
        }
        __syncthreads();
        if (t == 0) {
            float sa = 0.f;
            #pragma unroll
            for (int mm = 0; mm < MM; mm++) sa += s_a[mm];
            s_w[0] = s_a[blkm % MM] / sa / (float)(SS * BB);
        }
        __syncthreads();
        float w = s_w[0];

        double acc = 0.0;
        for (int s = t; s < SS; s += 128) {
            const float* base = g_dpart + (blkm * CHUNKS) * SS + s;
            float v = base[0];
            #pragma unroll
            for (int c = 1; c < CHUNKS; c++) v = fminf(v, base[c * SS]);
            v = (v >= 1e30f) ? 0.f : v;
            acc += (double)(v * w);
        }
        part = blockReduceSumD(acc);
    }

    if (t == 0) g_part[bid] = part;
    __threadfence();
    if (t == 0) {
        unsigned tk = atomicAdd(&g_cnt, 1u);
        s_last = (tk == (unsigned)(TAIL_BLOCKS - 1));
    }
    __syncthreads();

    if (s_last && t == 0) {
        double p2p = 0.0, prim = 0.0;
        for (int i = 0; i < TAIL_P2P; i++)  p2p  += __ldcg(&g_part[i]);
        for (int i = TAIL_P2P; i < TAIL_BLOCKS; i++) prim += __ldcg(&g_part[i]);
        double embv = __ldcg(&g_emb);
        out[0] = (float)(p2p + prim + embv);
        out[1] = (float)p2p;
        out[2] = (float)prim;
        out[3] = 0.f;
        out[4] = (float)embv;
        g_cnt = 0;   // reset for next graph replay
    }
}

// ---------------- launch ----------------
extern "C" void kernel_launch(void* const* d_in, const int* in_sizes, int n_in,
                              void* d_out, int out_size)
{
    const float* pcl    = (const float*)d_in[0];
    const float* trans  = (const float*)d_in[1];
    const float* rot    = (const float*)d_in[2];
    const float* size   = (const float*)d_in[3];
    const float* shape  = (const float*)d_in[4];
    const float* deform = (const float*)d_in[5];
    const float* prob   = (const float*)d_in[6];
    const float* emb    = (const float*)d_in[7];

    k_fused<<<FUSED_BLOCKS + 1, 256>>>(pcl, trans, rot, size, shape, deform, emb);
    k_tail <<<TAIL_BLOCKS, 128>>>(prob, size, emb, (float*)d_out);
}

// round 9
// speedup vs baseline: 1.0761x; 1.0235x over previous
#include <cuda_runtime.h>
#include <math.h>

#define BB 4
#define NN 2048
#define MM 16
#define SS 200
#define CHUNKS 8            // N split into 8 chunks of 256

#define PROD_WORK    (BB * MM * CHUNKS)        // 512 merged work blocks
#define PROD_BLOCKS  (PROD_WORK + 1)           // +1 emb block = 513
#define TAIL_P2P     32                        // 32 blocks x 256 points
#define TAIL_PRIM    (BB * MM)                 // 64 blocks, one per (b,m)
#define TAIL_BLOCKS  (TAIL_P2P + TAIL_PRIM)    // 96
#define GRID_BLOCKS  (PROD_BLOCKS + TAIL_BLOCKS)  // 609

typedef unsigned long long ull;

// ---------------- device scratch ----------------
__device__ float    g_dv[BB * NN * MM];                 // TRANSPOSED: [(b*NN+n)*MM + m]
__device__ float    g_dpart[BB * MM * CHUNKS * SS];     // per-chunk partial min-over-n
__device__ double   g_part[TAIL_BLOCKS];                // per-tail-block partial sums
__device__ double   g_emb;
__device__ unsigned g_cnt1;                             // producer ticket (self-resetting)
__device__ unsigned g_cnt2;                             // tail ticket (self-resetting)

// ---------------- f32x2 packed helpers (sm_100) ----------------
__device__ __forceinline__ ull pk2(float lo, float hi) {
    ull r; asm("mov.b64 %0, {%1, %2};" : "=l"(r) : "f"(lo), "f"(hi)); return r;
}
__device__ __forceinline__ ull fma2(ull a, ull b, ull c) {
    ull r; asm("fma.rn.f32x2 %0, %1, %2, %3;" : "=l"(r) : "l"(a), "l"(b), "l"(c)); return r;
}
__device__ __forceinline__ void upk2(ull v, float& lo, float& hi) {
    asm("mov.b64 {%0, %1}, %2;" : "=f"(lo), "=f"(hi) : "l"(v));
}

__device__ __forceinline__ float fexp_f(float x, float p) {
    float s = (x > 0.f) ? 1.f : ((x < 0.f) ? -1.f : 0.f);
    return s * powf(fabsf(x) + 1e-6f, p);
}

__device__ __forceinline__ double blockReduceSumD(double v) {
    __shared__ double sh[32];
    int lane = threadIdx.x & 31, wid = threadIdx.x >> 5;
    #pragma unroll
    for (int o = 16; o; o >>= 1) v += __shfl_down_sync(0xffffffffu, v, o);
    if (lane == 0) sh[wid] = v;
    __syncthreads();
    int nw = (blockDim.x + 31) >> 5;
    v = (threadIdx.x < nw) ? sh[threadIdx.x] : 0.0;
    if (wid == 0) {
        #pragma unroll
        for (int o = 16; o; o >>= 1) v += __shfl_down_sync(0xffffffffu, v, o);
    }
    __syncthreads();
    return v;
}

// argmax_i emb[b][i][m]  (first max on ties)
__device__ __forceinline__ int argmax_col(const float* __restrict__ emb, int b, int m) {
    int j = 0;
    float best = emb[(b * MM + 0) * MM + m];
    #pragma unroll
    for (int i = 1; i < MM; i++) {
        float v = emb[(b * MM + i) * MM + m];
        if (v > best) { best = v; j = i; }
    }
    return j;
}

// ---------------- THE kernel ----------------
__global__ void __launch_bounds__(256, 4) k_all(const float* __restrict__ pcl,
                                                const float* __restrict__ trans,
                                                const float* __restrict__ rot,
                                                const float* __restrict__ size,
                                                const float* __restrict__ shape,
                                                const float* __restrict__ deform,
                                                const float* __restrict__ prob,
                                                const float* __restrict__ emb,
                                                float* __restrict__ out)
{
    int bid = blockIdx.x, t = threadIdx.x;

    // ===================== PRODUCER BLOCKS =====================
    if (bid < PROD_BLOCKS) {
        if (bid == PROD_WORK) {
            // ---- embeddings regularizer ----
            double c1 = 0.0, c2 = 0.0, c3 = 0.0;
            if (t < BB * MM) {
                int bb = t / MM, k = t % MM;
                float s1 = 0.f, s2 = 0.f;
                for (int i = 0; i < MM; i++) {
                    s1 += emb[(bb * MM + i) * MM + k];
                    s2 += emb[(bb * MM + k) * MM + i];
                }
                float d1 = s1 - 1.f, d2 = s2 - 1.f;
                c1 = (double)(d1 * d1);
                c2 = (double)(d2 * d2);
            }
            for (int i = t; i < BB * MM * MM; i += 256) {
                float v = emb[i];
                c3 += (double)(v * (1.f - v));
            }
            double r1 = blockReduceSumD(c1);
            double r2 = blockReduceSumD(c2);
            double r3 = blockReduceSumD(c3);
            if (t == 0) {
                g_emb = r1 / (double)(BB * MM) + 10.0 * r2 / (double)(BB * MM)
                      + r3 / (double)(BB * MM * MM);
                __threadfence();
                atomicAdd(&g_cnt1, 1u);
            }
            return;
        }

        // merged work block: both distance loops for (blkm, chunk)
        __shared__ ulonglong2 s_qA[SS / 2], s_qB[SS / 2];   // samples, packed pairs
        __shared__ ulonglong2 s_uA[128], s_uB[128];         // transformed points, packed
        __shared__ float  s_R[9], s_t[3], s_par[7];

        int blkm  = bid / CHUNKS;
        int chunk = bid % CHUNKS;
        int b     = blkm / MM, m = blkm % MM;

        if (t == 0) {
            int j = argmax_col(emb, b, m);
            const float* q = rot + blkm * 4;
            float w = q[0], x = q[1], y = q[2], z = q[3];
            float inv = rsqrtf(w * w + x * x + y * y + z * z);
            w *= inv; x *= inv; y *= inv; z *= inv;
            s_R[0] = 1.f - 2.f * (y * y + z * z); s_R[1] = 2.f * (x * y - w * z); s_R[2] = 2.f * (x * z + w * y);
            s_R[3] = 2.f * (x * y + w * z); s_R[4] = 1.f - 2.f * (x * x + z * z); s_R[5] = 2.f * (y * z - w * x);
            s_R[6] = 2.f * (x * z - w * y); s_R[7] = 2.f * (y * z + w * x); s_R[8] = 1.f - 2.f * (x * x + y * y);
            s_t[0] = trans[blkm * 3 + 0]; s_t[1] = trans[blkm * 3 + 1]; s_t[2] = trans[blkm * 3 + 2];
            const float* sz3 = size   + (b * MM + j) * 3;
            const float* sh2 = shape  + (b * MM + j) * 2;
            const float* df2 = deform + (b * MM + j) * 2;
            s_par[0] = sh2[0]; s_par[1] = sh2[1];
            s_par[2] = sz3[0]; s_par[3] = sz3[1]; s_par[4] = sz3[2];
            s_par[5] = df2[0]; s_par[6] = df2[1];
        }
        __syncthreads();

        // sample points -> packed smem (t < SS)
        if (t < SS) {
            float e1 = s_par[0], e2 = s_par[1];
            float sx = s_par[2], sy = s_par[3], szv = s_par[4];
            float dfx = s_par[5], dfy = s_par[6];
            double stepE = (M_PI - 0.1) / (double)(SS - 1);
            double stepO = (2.0 * M_PI - 0.1) / (double)(SS - 1);
            float eta = (float)(-M_PI / 2.0 + 0.05 + t * stepE);
            float omg = (float)(-M_PI + 0.05 + t * stepO);
            float ce = cosf(eta), se = sinf(eta), co = cosf(omg), so = sinf(omg);
            float fce = fexp_f(ce, e1);
            float x = sx * fce * fexp_f(co, e2);
            float y = sy * fce * fexp_f(so, e2);
            float z = szv * fexp_f(se, e1);
            float fx = dfx / szv * z + 1.f;
            float fy = dfy / szv * z + 1.f;
            float X = x * fx, Y = y * fy, Z = z;
            float W = fmaf(X, X, fmaf(Y, Y, Z * Z));
            int p = t >> 1, h = t & 1;
            float* A = (float*)s_qA;  float* Bf = (float*)s_qB;
            A[4 * p + h]     = X;  A[4 * p + 2 + h] = Y;
            Bf[4 * p + h]    = Z;  Bf[4 * p + 2 + h] = W;
        }

        // transform my point once: registers + packed smem
        int n = chunk * 256 + t;
        const float* P = pcl + (b * NN + n) * 3;
        float ax = P[0] - s_t[0], ay = P[1] - s_t[1], az = P[2] - s_t[2];
        float ux = s_R[0] * ax + s_R[1] * ay + s_R[2] * az;
        float uy = s_R[3] * ax + s_R[4] * ay + s_R[5] * az;
        float uz = s_R[6] * ax + s_R[7] * ay + s_R[8] * az;
        float uw = fmaf(ux, ux, fmaf(uy, uy, uz * uz));
        {
            int p = t >> 1, h = t & 1;
            float* A = (float*)s_uA;  float* Bf = (float*)s_uB;
            A[4 * p + h]     = ux; A[4 * p + 2 + h] = uy;
            Bf[4 * p + h]    = uz; Bf[4 * p + 2 + h] = uw;
        }
        __syncthreads();

        // ---------- p2p: min over S (point in regs, samples broadcast from smem) ----------
        {
            ull tx2p = pk2(-2.f * ux, -2.f * ux);
            ull ty2p = pk2(-2.f * uy, -2.f * uy);
            ull tz2p = pk2(-2.f * uz, -2.f * uz);

            float m0 = 3.4e38f, m1 = m0, m2 = m0, m3 = m0;
            #pragma unroll 5
            for (int p = 0; p < SS / 2; p += 2) {
                ulonglong2 a0 = s_qA[p],     b0 = s_qB[p];
                ulonglong2 a1 = s_qA[p + 1], b1 = s_qB[p + 1];
                ull v0 = fma2(b0.x, tz2p, b0.y);
                v0 = fma2(a0.y, ty2p, v0);
                v0 = fma2(a0.x, tx2p, v0);
                float l0, h0; upk2(v0, l0, h0);
                m0 = fminf(m0, l0); m1 = fminf(m1, h0);
                ull v1 = fma2(b1.x, tz2p, b1.y);
                v1 = fma2(a1.y, ty2p, v1);
                v1 = fma2(a1.x, tx2p, v1);
                float l1, h1; upk2(v1, l1, h1);
                m2 = fminf(m2, l1); m3 = fminf(m3, h1);
            }
            float d = fminf(fminf(m0, m1), fminf(m2, m3)) + uw;
            d = fmaxf(d, 0.f);
            g_dv[(b * NN + n) * MM + m] = d;   // transposed store
        }

        // ---------- prim: partial min over this chunk's 256 points ----------
        if (t < SS) {
            int p0 = t >> 1, h0i = t & 1;
            const float* A = (const float*)s_qA;  const float* Bf = (const float*)s_qB;
            float qx = A[4 * p0 + h0i], qy = A[4 * p0 + 2 + h0i];
            float qz = Bf[4 * p0 + h0i], qw = Bf[4 * p0 + 2 + h0i];
            ull qx2p = pk2(-2.f * qx, -2.f * qx);
            ull qy2p = pk2(-2.f * qy, -2.f * qy);
            ull qz2p = pk2(-2.f * qz, -2.f * qz);

            float m0 = 3.4e38f, m1 = m0, m2 = m0, m3 = m0;
            #pragma unroll 4
            for (int p = 0; p < 128; p += 2) {
                ulonglong2 a0 = s_uA[p],     b0 = s_uB[p];
                ulonglong2 a1 = s_uA[p + 1], b1 = s_uB[p + 1];
                ull v0 = fma2(b0.x, qz2p, b0.y);
                v0 = fma2(a0.y, qy2p, v0);
                v0 = fma2(a0.x, qx2p, v0);
                float l0, h0; upk2(v0, l0, h0);
                m0 = fminf(m0, l0); m1 = fminf(m1, h0);
                ull v1 = fma2(b1.x, qz2p, b1.y);
                v1 = fma2(a1.y, qy2p, v1);
                v1 = fma2(a1.x, qx2p, v1);
                float l1, h1; upk2(v1, l1, h1);
                m2 = fminf(m2, l1); m3 = fminf(m3, h1);
            }
            float d = fminf(fminf(m0, m1), fminf(m2, m3)) + qw;
            d = fmaxf(d, 0.f);
            g_dpart[(blkm * CHUNKS + chunk) * SS + t] = d;
        }

        __syncthreads();
        if (t == 0) {
            __threadfence();
            atomicAdd(&g_cnt1, 1u);
        }
        return;
    }

    // ===================== TAIL BLOCKS (spin until producers done) =====================
    if (t == 0) {
        volatile unsigned* c = &g_cnt1;
        while (*c < (unsigned)PROD_BLOCKS) __nanosleep(64);
    }
    __syncthreads();
    __threadfence();   // order subsequent reads after observed release

    int pid = bid - PROD_BLOCKS;   // 0..95
    double part = 0.0;

    if (pid < TAIL_P2P) {
        // ---- p2p weighting: 32 blocks x 256 points ----
        __shared__ float s_p[MM];
        int b = pid / 8, c8 = pid % 8;
        if (t < MM) s_p[t] = prob[b * MM + t];
        __syncthreads();

        int n = c8 * 256 + t;
        const float4* dvp = (const float4*)&g_dv[(b * NN + n) * MM];
        float dv[MM], pv[MM];
        float4 d0 = __ldcg(&dvp[0]), d1 = __ldcg(&dvp[1]);
        float4 d2 = __ldcg(&dvp[2]), d3 = __ldcg(&dvp[3]);
        ((float4*)dv)[0] = d0; ((float4*)dv)[1] = d1;
        ((float4*)dv)[2] = d2; ((float4*)dv)[3] = d3;
        #pragma unroll
        for (int mm = 0; mm < MM; mm++) pv[mm] = s_p[mm];

        float acc = 0.f;
        #pragma unroll
        for (int mm = 0; mm < MM; mm++) {
            float w = pv[mm];
            #pragma unroll
            for (int j = 0; j < MM; j++) {
                if (j == mm) continue;
                bool before = (dv[j] < dv[mm]) || (dv[j] == dv[mm] && j < mm);
                w *= before ? (1.f - pv[j]) : 1.f;
            }
            acc = fmaf(dv[mm], w, acc);
        }
        part = blockReduceSumD((double)acc) / (double)(BB * NN);
    } else {
        // ---- prim reduction: one block per (b,m) ----
        int blkm = pid - TAIL_P2P;
        int b = blkm / MM;
        __shared__ float s_a[MM];
        __shared__ float s_w[1];

        if (t < MM) {
            int j = argmax_col(emb, b, t);
            const float* sz3 = size + (b * MM + j) * 3;
            float a0 = sz3[0], a1 = sz3[1], a2 = sz3[2];
            float ar = powf(a0 * a1, 1.6f) / 3.f + powf(a0 * a2, 1.6f) / 3.f + powf(a1 * a2, 1.6f) / 3.f;
            s_a[t] = 4.f * (float)M_PI * powf(ar, 0.625f);
        }
        __syncthreads();
        if (t == 0) {
            float sa = 0.f;
            #pragma unroll
            for (int mm = 0; mm < MM; mm++) sa += s_a[mm];
            s_w[0] = s_a[blkm % MM] / sa / (float)(SS * BB);
        }
        __syncthreads();
        float w = s_w[0];

        double acc = 0.0;
        if (t < SS) {
            const float* base = g_dpart + (blkm * CHUNKS) * SS + t;
            float v = __ldcg(&base[0]);
            #pragma unroll
            for (int c = 1; c < CHUNKS; c++) v = fminf(v, __ldcg(&base[c * SS]));
            v = (v >= 1e30f) ? 0.f : v;
            acc = (double)(v * w);
        }
        part = blockReduceSumD(acc);
    }

    __shared__ bool s_last;
    if (t == 0) g_part[pid] = part;
    __threadfence();
    if (t == 0) {
        unsigned tk = atomicAdd(&g_cnt2, 1u);
        s_last = (tk == (unsigned)(TAIL_BLOCKS - 1));
    }
    __syncthreads();

    if (s_last && t == 0) {
        double p2p = 0.0, prim = 0.0;
        for (int i = 0; i < TAIL_P2P; i++)  p2p  += __ldcg(&g_part[i]);
        for (int i = TAIL_P2P; i < TAIL_BLOCKS; i++) prim += __ldcg(&g_part[i]);
        double embv = __ldcg(&g_emb);
        out[0] = (float)(p2p + prim + embv);
        out[1] = (float)p2p;
        out[2] = (float)prim;
        out[3] = 0.f;
        out[4] = (float)embv;
        g_cnt1 = 0;   // reset for next graph replay
        g_cnt2 = 0;
    }
}

// ---------------- launch ----------------
extern "C" void kernel_launch(void* const* d_in, const int* in_sizes, int n_in,
                              void* d_out, int out_size)
{
    const float* pcl    = (const float*)d_in[0];
    const float* trans  = (const float*)d_in[1];
    const float* rot    = (const float*)d_in[2];
    const float* size   = (const float*)d_in[3];
    const float* shape  = (const float*)d_in[4];
    const float* deform = (const float*)d_in[5];
    const float* prob   = (const float*)d_in[6];
    const float* emb    = (const float*)d_in[7];

    k_all<<<GRID_BLOCKS, 256>>>(pcl, trans, rot, size, shape, deform, prob, emb,
                                (float*)d_out);
}

// round 10
// speedup vs baseline: 1.3535x; 1.2577x over previous
#include <cuda_runtime.h>
#include <math.h>

#define BB 4
#define NN 2048
#define MM 16
#define SS 200
#define PTS 512             // points per producer block
#define CHUNKS (NN / PTS)   // 4

#define PROD_WORK    (BB * MM * CHUNKS)        // 256 merged work blocks
#define PROD_BLOCKS  (PROD_WORK + 1)           // +1 emb block = 257
#define TAIL_P2P     32                        // 32 blocks x 256 points
#define TAIL_PRIM    (BB * MM)                 // 64 blocks, one per (b,m)
#define TAIL_BLOCKS  (TAIL_P2P + TAIL_PRIM)    // 96
#define GRID_BLOCKS  (PROD_BLOCKS + TAIL_BLOCKS)  // 353

typedef unsigned long long ull;

// ---------------- device scratch ----------------
__device__ float    g_dv[BB * NN * MM];                 // TRANSPOSED: [(b*NN+n)*MM + m]
__device__ float    g_dpart[BB * MM * CHUNKS * SS];     // per-chunk partial min-over-n
__device__ double   g_part[TAIL_BLOCKS];                // per-tail-block partial sums
__device__ double   g_emb;
__device__ unsigned g_cnt1;                             // producer ticket (self-resetting)
__device__ unsigned g_cnt2;                             // tail ticket (self-resetting)

// ---------------- f32x2 packed helpers (sm_100) ----------------
__device__ __forceinline__ ull pk2(float lo, float hi) {
    ull r; asm("mov.b64 %0, {%1, %2};" : "=l"(r) : "f"(lo), "f"(hi)); return r;
}
__device__ __forceinline__ ull fma2(ull a, ull b, ull c) {
    ull r; asm("fma.rn.f32x2 %0, %1, %2, %3;" : "=l"(r) : "l"(a), "l"(b), "l"(c)); return r;
}
__device__ __forceinline__ void upk2(ull v, float& lo, float& hi) {
    asm("mov.b64 {%0, %1}, %2;" : "=f"(lo), "=f"(hi) : "l"(v));
}

__device__ __forceinline__ float fexp_f(float x, float p) {
    float s = (x > 0.f) ? 1.f : ((x < 0.f) ? -1.f : 0.f);
    return s * powf(fabsf(x) + 1e-6f, p);
}

__device__ __forceinline__ double blockReduceSumD(double v) {
    __shared__ double sh[32];
    int lane = threadIdx.x & 31, wid = threadIdx.x >> 5;
    #pragma unroll
    for (int o = 16; o; o >>= 1) v += __shfl_down_sync(0xffffffffu, v, o);
    if (lane == 0) sh[wid] = v;
    __syncthreads();
    int nw = (blockDim.x + 31) >> 5;
    v = (threadIdx.x < nw) ? sh[threadIdx.x] : 0.0;
    if (wid == 0) {
        #pragma unroll
        for (int o = 16; o; o >>= 1) v += __shfl_down_sync(0xffffffffu, v, o);
    }
    __syncthreads();
    return v;
}

// argmax_i emb[b][i][m]  (first max on ties)
__device__ __forceinline__ int argmax_col(const float* __restrict__ emb, int b, int m) {
    int j = 0;
    float best = emb[(b * MM + 0) * MM + m];
    #pragma unroll
    for (int i = 1; i < MM; i++) {
        float v = emb[(b * MM + i) * MM + m];
        if (v > best) { best = v; j = i; }
    }
    return j;
}

// ---------------- THE kernel ----------------
__global__ void __launch_bounds__(256, 3) k_all(const float* __restrict__ pcl,
                                                const float* __restrict__ trans,
                                                const float* __restrict__ rot,
                                                const float* __restrict__ size,
                                                const float* __restrict__ shape,
                                                const float* __restrict__ deform,
                                                const float* __restrict__ prob,
                                                const float* __restrict__ emb,
                                                float* __restrict__ out)
{
    int bid = blockIdx.x, t = threadIdx.x;

    // ===================== PRODUCER BLOCKS =====================
    if (bid < PROD_BLOCKS) {
        if (bid == PROD_WORK) {
            // ---- embeddings regularizer ----
            double c1 = 0.0, c2 = 0.0, c3 = 0.0;
            if (t < BB * MM) {
                int bb = t / MM, k = t % MM;
                float s1 = 0.f, s2 = 0.f;
                for (int i = 0; i < MM; i++) {
                    s1 += emb[(bb * MM + i) * MM + k];
                    s2 += emb[(bb * MM + k) * MM + i];
                }
                float d1 = s1 - 1.f, d2 = s2 - 1.f;
                c1 = (double)(d1 * d1);
                c2 = (double)(d2 * d2);
            }
            for (int i = t; i < BB * MM * MM; i += 256) {
                float v = emb[i];
                c3 += (double)(v * (1.f - v));
            }
            double r1 = blockReduceSumD(c1);
            double r2 = blockReduceSumD(c2);
            double r3 = blockReduceSumD(c3);
            if (t == 0) {
                g_emb = r1 / (double)(BB * MM) + 10.0 * r2 / (double)(BB * MM)
                      + r3 / (double)(BB * MM * MM);
                __threadfence();
                atomicAdd(&g_cnt1, 1u);
            }
            return;
        }

        // merged work block: both distance loops for (blkm, chunk of 512 points)
        __shared__ ulonglong2 s_qA[SS / 2], s_qB[SS / 2];     // samples, packed pairs
        __shared__ ulonglong2 s_uA[PTS / 2], s_uB[PTS / 2];   // transformed points, packed
        __shared__ float  s_R[9], s_t[3], s_par[7];

        int blkm  = bid / CHUNKS;
        int chunk = bid % CHUNKS;
        int b     = blkm / MM, m = blkm % MM;

        if (t == 0) {
            int j = argmax_col(emb, b, m);
            const float* q = rot + blkm * 4;
            float w = q[0], x = q[1], y = q[2], z = q[3];
            float inv = rsqrtf(w * w + x * x + y * y + z * z);
            w *= inv; x *= inv; y *= inv; z *= inv;
            s_R[0] = 1.f - 2.f * (y * y + z * z); s_R[1] = 2.f * (x * y - w * z); s_R[2] = 2.f * (x * z + w * y);
            s_R[3] = 2.f * (x * y + w * z); s_R[4] = 1.f - 2.f * (x * x + z * z); s_R[5] = 2.f * (y * z - w * x);
            s_R[6] = 2.f * (x * z - w * y); s_R[7] = 2.f * (y * z + w * x); s_R[8] = 1.f - 2.f * (x * x + y * y);
            s_t[0] = trans[blkm * 3 + 0]; s_t[1] = trans[blkm * 3 + 1]; s_t[2] = trans[blkm * 3 + 2];
            const float* sz3 = size   + (b * MM + j) * 3;
            const float* sh2 = shape  + (b * MM + j) * 2;
            const float* df2 = deform + (b * MM + j) * 2;
            s_par[0] = sh2[0]; s_par[1] = sh2[1];
            s_par[2] = sz3[0]; s_par[3] = sz3[1]; s_par[4] = sz3[2];
            s_par[5] = df2[0]; s_par[6] = df2[1];
        }
        __syncthreads();

        // sample points -> packed smem (t < SS)
        if (t < SS) {
            float e1 = s_par[0], e2 = s_par[1];
            float sx = s_par[2], sy = s_par[3], szv = s_par[4];
            float dfx = s_par[5], dfy = s_par[6];
            double stepE = (M_PI - 0.1) / (double)(SS - 1);
            double stepO = (2.0 * M_PI - 0.1) / (double)(SS - 1);
            float eta = (float)(-M_PI / 2.0 + 0.05 + t * stepE);
            float omg = (float)(-M_PI + 0.05 + t * stepO);
            float ce = cosf(eta), se = sinf(eta), co = cosf(omg), so = sinf(omg);
            float fce = fexp_f(ce, e1);
            float x = sx * fce * fexp_f(co, e2);
            float y = sy * fce * fexp_f(so, e2);
            float z = szv * fexp_f(se, e1);
            float fx = dfx / szv * z + 1.f;
            float fy = dfy / szv * z + 1.f;
            float X = x * fx, Y = y * fy, Z = z;
            float W = fmaf(X, X, fmaf(Y, Y, Z * Z));
            int p = t >> 1, h = t & 1;
            float* A = (float*)s_qA;  float* Bf = (float*)s_qB;
            A[4 * p + h]     = X;  A[4 * p + 2 + h] = Y;
            Bf[4 * p + h]    = Z;  Bf[4 * p + 2 + h] = W;
        }

        // transform TWO points per thread (local l0 = t, l1 = t + 256)
        float R0 = s_R[0], R1 = s_R[1], R2 = s_R[2];
        float R3 = s_R[3], R4 = s_R[4], R5 = s_R[5];
        float R6 = s_R[6], R7 = s_R[7], R8 = s_R[8];
        // NOTE: s_R/s_t read after __syncthreads above — safe.
        float ux0, uy0, uz0, uw0, ux1, uy1, uz1, uw1;
        {
            int n0 = chunk * PTS + t;
            const float* P0 = pcl + (b * NN + n0) * 3;
            float ax = P0[0] - s_t[0], ay = P0[1] - s_t[1], az = P0[2] - s_t[2];
            ux0 = R0 * ax + R1 * ay + R2 * az;
            uy0 = R3 * ax + R4 * ay + R5 * az;
            uz0 = R6 * ax + R7 * ay + R8 * az;
            uw0 = fmaf(ux0, ux0, fmaf(uy0, uy0, uz0 * uz0));
            const float* P1 = P0 + 256 * 3;
            float bx = P1[0] - s_t[0], by = P1[1] - s_t[1], bz = P1[2] - s_t[2];
            ux1 = R0 * bx + R1 * by + R2 * bz;
            uy1 = R3 * bx + R4 * by + R5 * bz;
            uz1 = R6 * bx + R7 * by + R8 * bz;
            uw1 = fmaf(ux1, ux1, fmaf(uy1, uy1, uz1 * uz1));
            int p = t >> 1, h = t & 1;
            float* A = (float*)s_uA;  float* Bf = (float*)s_uB;
            A[4 * p + h]          = ux0; A[4 * p + 2 + h]        = uy0;
            Bf[4 * p + h]         = uz0; Bf[4 * p + 2 + h]       = uw0;
            A[4 * (p + 128) + h]  = ux1; A[4 * (p + 128) + 2 + h] = uy1;
            Bf[4 * (p + 128) + h] = uz1; Bf[4 * (p + 128) + 2 + h] = uw1;
        }
        __syncthreads();

        // ---------- p2p: min over S for BOTH points (each LDS feeds 2 points) ----------
        {
            ull x0p = pk2(-2.f * ux0, -2.f * ux0);
            ull y0p = pk2(-2.f * uy0, -2.f * uy0);
            ull z0p = pk2(-2.f * uz0, -2.f * uz0);
            ull x1p = pk2(-2.f * ux1, -2.f * ux1);
            ull y1p = pk2(-2.f * uy1, -2.f * uy1);
            ull z1p = pk2(-2.f * uz1, -2.f * uz1);

            float m00 = 3.4e38f, m01 = m00, m02 = m00, m03 = m00;
            float m10 = m00, m11 = m00, m12 = m00, m13 = m00;
            #pragma unroll 5
            for (int p = 0; p < SS / 2; p += 2) {
                ulonglong2 la0 = s_qA[p],     lb0 = s_qB[p];
                ulonglong2 la1 = s_qA[p + 1], lb1 = s_qB[p + 1];
                ull v; float lo, hi;
                v = fma2(la0.x, x0p, fma2(la0.y, y0p, fma2(lb0.x, z0p, lb0.y)));
                upk2(v, lo, hi); m00 = fminf(m00, lo); m01 = fminf(m01, hi);
                v = fma2(la0.x, x1p, fma2(la0.y, y1p, fma2(lb0.x, z1p, lb0.y)));
                upk2(v, lo, hi); m10 = fminf(m10, lo); m11 = fminf(m11, hi);
                v = fma2(la1.x, x0p, fma2(la1.y, y0p, fma2(lb1.x, z0p, lb1.y)));
                upk2(v, lo, hi); m02 = fminf(m02, lo); m03 = fminf(m03, hi);
                v = fma2(la1.x, x1p, fma2(la1.y, y1p, fma2(lb1.x, z1p, lb1.y)));
                upk2(v, lo, hi); m12 = fminf(m12, lo); m13 = fminf(m13, hi);
            }
            int n0 = chunk * PTS + t;
            float d0 = fminf(fminf(m00, m01), fminf(m02, m03)) + uw0;
            float d1 = fminf(fminf(m10, m11), fminf(m12, m13)) + uw1;
            d0 = fmaxf(d0, 0.f);
            d1 = fmaxf(d1, 0.f);
            g_dv[(b * NN + n0) * MM + m]       = d0;
            g_dv[(b * NN + n0 + 256) * MM + m] = d1;
        }

        // ---------- prim: TWO samples per thread over 512 points ----------
        if (t < SS / 2) {
            int p0 = t >> 1, h0 = t & 1;          // sample s0 = t
            int p1 = p0 + 50;                     // sample s1 = t + 100 (same parity)
            const float* A = (const float*)s_qA;  const float* Bf = (const float*)s_qB;
            float qx0 = A[4 * p0 + h0], qy0 = A[4 * p0 + 2 + h0];
            float qz0 = Bf[4 * p0 + h0], qw0 = Bf[4 * p0 + 2 + h0];
            float qx1 = A[4 * p1 + h0], qy1 = A[4 * p1 + 2 + h0];
            float qz1 = Bf[4 * p1 + h0], qw1 = Bf[4 * p1 + 2 + h0];
            ull x0p = pk2(-2.f * qx0, -2.f * qx0);
            ull y0p = pk2(-2.f * qy0, -2.f * qy0);
            ull z0p = pk2(-2.f * qz0, -2.f * qz0);
            ull x1p = pk2(-2.f * qx1, -2.f * qx1);
            ull y1p = pk2(-2.f * qy1, -2.f * qy1);
            ull z1p = pk2(-2.f * qz1, -2.f * qz1);

            float a0 = 3.4e38f, a1 = a0, a2 = a0, a3 = a0;   // s0
            float c0 = a0, c1 = a0, c2 = a0, c3 = a0;        // s1
            #pragma unroll 4
            for (int p = 0; p < PTS / 2; p += 2) {
                ulonglong2 la0 = s_uA[p],     lb0 = s_uB[p];
                ulonglong2 la1 = s_uA[p + 1], lb1 = s_uB[p + 1];
                ull v; float lo, hi;
                v = fma2(la0.x, x0p, fma2(la0.y, y0p, fma2(lb0.x, z0p, lb0.y)));
                upk2(v, lo, hi); a0 = fminf(a0, lo); a1 = fminf(a1, hi);
                v = fma2(la0.x, x1p, fma2(la0.y, y1p, fma2(lb0.x, z1p, lb0.y)));
                upk2(v, lo, hi); c0 = fminf(c0, lo); c1 = fminf(c1, hi);
                v = fma2(la1.x, x0p, fma2(la1.y, y0p, fma2(lb1.x, z0p, lb1.y)));
                upk2(v, lo, hi); a2 = fminf(a2, lo); a3 = fminf(a3, hi);
                v = fma2(la1.x, x1p, fma2(la1.y, y1p, fma2(lb1.x, z1p, lb1.y)));
                upk2(v, lo, hi); c2 = fminf(c2, lo); c3 = fminf(c3, hi);
            }
            float d0 = fminf(fminf(a0, a1), fminf(a2, a3)) + qw0;
            float d1 = fminf(fminf(c0, c1), fminf(c2, c3)) + qw1;
            d0 = fmaxf(d0, 0.f);
            d1 = fmaxf(d1, 0.f);
            float* dst = g_dpart + (blkm * CHUNKS + chunk) * SS;
            dst[t]       = d0;
            dst[t + 100] = d1;
        }

        __syncthreads();
        if (t == 0) {
            __threadfence();
            atomicAdd(&g_cnt1, 1u);
        }
        return;
    }

    // ===================== TAIL BLOCKS (spin until producers done) =====================
    if (t == 0) {
        volatile unsigned* c = &g_cnt1;
        while (*c < (unsigned)PROD_BLOCKS) __nanosleep(64);
    }
    __syncthreads();
    __threadfence();   // order subsequent reads after observed release

    int pid = bid - PROD_BLOCKS;   // 0..95
    double part = 0.0;

    if (pid < TAIL_P2P) {
        // ---- p2p weighting: 32 blocks x 256 points ----
        __shared__ float s_p[MM];
        int b = pid / 8, c8 = pid % 8;
        if (t < MM) s_p[t] = prob[b * MM + t];
        __syncthreads();

        int n = c8 * 256 + t;
        const float4* dvp = (const float4*)&g_dv[(b * NN + n) * MM];
        float dv[MM], pv[MM];
        float4 d0 = __ldcg(&dvp[0]), d1 = __ldcg(&dvp[1]);
        float4 d2 = __ldcg(&dvp[2]), d3 = __ldcg(&dvp[3]);
        ((float4*)dv)[0] = d0; ((float4*)dv)[1] = d1;
        ((float4*)dv)[2] = d2; ((float4*)dv)[3] = d3;
        #pragma unroll
        for (int mm = 0; mm < MM; mm++) pv[mm] = s_p[mm];

        float acc = 0.f;
        #pragma unroll
        for (int mm = 0; mm < MM; mm++) {
            float w = pv[mm];
            #pragma unroll
            for (int j = 0; j < MM; j++) {
                if (j == mm) continue;
                bool before = (dv[j] < dv[mm]) || (dv[j] == dv[mm] && j < mm);
                w *= before ? (1.f - pv[j]) : 1.f;
            }
            acc = fmaf(dv[mm], w, acc);
        }
        part = blockReduceSumD((double)acc) / (double)(BB * NN);
    } else {
        // ---- prim reduction: one block per (b,m) ----
        int blkm = pid - TAIL_P2P;
        int b = blkm / MM;
        __shared__ float s_a[MM];
        __shared__ float s_w[1];

        if (t < MM) {
            int j = argmax_col(emb, b, t);
            const float* sz3 = size + (b * MM + j) * 3;
            float a0 = sz3[0], a1 = sz3[1], a2 = sz3[2];
            float ar = powf(a0 * a1, 1.6f) / 3.f + powf(a0 * a2, 1.6f) / 3.f + powf(a1 * a2, 1.6f) / 3.f;
            s_a[t] = 4.f * (float)M_PI * powf(ar, 0.625f);
        }
        __syncthreads();
        if (t == 0) {
            float sa = 0.f;
            #pragma unroll
            for (int mm = 0; mm < MM; mm++) sa += s_a[mm];
            s_w[0] = s_a[blkm % MM] / sa / (float)(SS * BB);
        }
        __syncthreads();
        float w = s_w[0];

        double acc = 0.0;
        if (t < SS) {
            const float* base = g_dpart + (blkm * CHUNKS) * SS + t;
            float v = __ldcg(&base[0]);
            #pragma unroll
            for (int c = 1; c < CHUNKS; c++) v = fminf(v, __ldcg(&base[c * SS]));
            v = (v >= 1e30f) ? 0.f : v;
            acc = (double)(v * w);
        }
        part = blockReduceSumD(acc);
    }

    __shared__ bool s_last;
    if (t == 0) g_part[pid] = part;
    __threadfence();
    if (t == 0) {
        unsigned tk = atomicAdd(&g_cnt2, 1u);
        s_last = (tk == (unsigned)(TAIL_BLOCKS - 1));
    }
    __syncthreads();

    if (s_last && t == 0) {
        double p2p = 0.0, prim = 0.0;
        for (int i = 0; i < TAIL_P2P; i++)  p2p  += __ldcg(&g_part[i]);
        for (int i = TAIL_P2P; i < TAIL_BLOCKS; i++) prim += __ldcg(&g_part[i]);
        double embv = __ldcg(&g_emb);
        out[0] = (float)(p2p + prim + embv);
        out[1] = (float)p2p;
        out[2] = (float)prim;
        out[3] = 0.f;
        out[4] = (float)embv;
        g_cnt1 = 0;   // reset for next graph replay
        g_cnt2 = 0;
    }
}

// ---------------- launch ----------------
extern "C" void kernel_launch(void* const* d_in, const int* in_sizes, int n_in,
                              void* d_out, int out_size)
{
    const float* pcl    = (const float*)d_in[0];
    const float* trans  = (const float*)d_in[1];
    const float* rot    = (const float*)d_in[2];
    const float* size   = (const float*)d_in[3];
    const float* shape  = (const float*)d_in[4];
    const float* deform = (const float*)d_in[5];
    const float* prob   = (const float*)d_in[6];
    const float* emb    = (const float*)d_in[7];

    k_all<<<GRID_BLOCKS, 256>>>(pcl, trans, rot, size, shape, deform, prob, emb,
                                (float*)d_out);
}